// round 12
// baseline (speedup 1.0000x reference)
#include <cuda_runtime.h>
#include <cuda_bf16.h>

// Seq2seq LSTM via mma.sync.m16n8k16.bf16, split-bf16 (hi+lo, 3 products),
// fp32 accumulation. 128 persistent CTAs = 16 slices x 8 M-groups.
// R11: warp = m32 x n32 x K-half (16 warps, 0.67 LDS.64/MMA); dual bounce
// buffers summed in the cell update.

typedef unsigned int u32;
typedef unsigned short u16;

#define HID 256
#define NB  8192
#define PLANE (NB * HID)
#define STR 136                    // u32 row stride (8 mod 32: conflict-free)

__device__ __align__(16) u32 g_Wh[2][1024][128];   // Whh hi pairs
__device__ __align__(16) u32 g_Wl[2][1024][128];   // Whh lo pairs
__device__ __align__(16) u32 g_Wxh[1024][8];       // Wih hi pairs
__device__ __align__(16) u32 g_Wxl[1024][8];       // Wih lo pairs
__device__ __align__(16) u32 g_xB[48][NB][16];     // x: hi(8)|lo(8) pairs
__device__ __align__(16) u32 g_hpack[2][PLANE];    // h: hi | lo<<16
__device__ int g_ctr[16 * 72];

// ---- helpers ---------------------------------------------------------------
__device__ __forceinline__ u32 prmt(u32 a, u32 b, u32 s) {
    u32 d;
    asm("prmt.b32 %0,%1,%2,%3;" : "=r"(d) : "r"(a), "r"(b), "r"(s));
    return d;
}
__device__ __forceinline__ void mma16816(float* d, u32 a0, u32 a1, u32 a2,
                                         u32 a3, u32 b0, u32 b1) {
    asm volatile(
        "mma.sync.aligned.m16n8k16.row.col.f32.bf16.bf16.f32 "
        "{%0,%1,%2,%3}, {%4,%5,%6,%7}, {%8,%9}, {%0,%1,%2,%3};"
        : "+f"(d[0]), "+f"(d[1]), "+f"(d[2]), "+f"(d[3])
        : "r"(a0), "r"(a1), "r"(a2), "r"(a3), "r"(b0), "r"(b1));
}
__device__ __forceinline__ float sigf(float x) {
    return __fdividef(1.0f, 1.0f + __expf(-x));
}
__device__ __forceinline__ float tanh_(float x) {
    return 1.0f - __fdividef(2.0f, __expf(2.0f * x) + 1.0f);
}
__device__ __forceinline__ void split16(float v, u16& h, u16& l) {
    __nv_bfloat16 hb = __float2bfloat16(v);
    __nv_bfloat16 lb = __float2bfloat16(v - __bfloat162float(hb));
    h = *(u16*)&hb; l = *(u16*)&lb;
}
__device__ __forceinline__ u32 packsplit(float v) {
    u16 h, l; split16(v, h, l);
    return (u32)h | ((u32)l << 16);
}
__device__ __forceinline__ float2 bf2f(u32 v) {
    return __bfloat1622float2(*(__nv_bfloat162*)&v);
}
// fragment-interleaved column: pair j -> storage col ((b0,b1) = one LDS.64)
__device__ __forceinline__ int scol(int j) {
    return (j & ~7) + ((j & 3) << 1) + ((j >> 2) & 1);
}

// ---- SMEM byte layout -------------------------------------------------------
#define OF_AU   1024            // Whi tile 128xSTR u32 = 69632
#define OF_AL   70656           // Wlo tile 69632
#define OF_AX   140288          // Wx tile 128x20 u32 = 10240 (alias: dense W)
#define OF_BX   150528          // xB tile 64x20 u32 = 5120
#define OF_BU   155648          // h_hi tile 64xSTR = 34816 (alias: bounce0/dense h)
#define OF_BL   190464          // h_lo tile 34816 (alias: bounce1)
#define SMEM_BYTES 225280

// ---------------------------------------------------------------------------
__global__ void prep_kernel(const float* __restrict__ x,
                            const float* __restrict__ Wih,
                            const float* __restrict__ Whhe,
                            const float* __restrict__ Whhd)
{
    const int S1 = 2 * 1024 * 128;
    const int S2 = S1 + 1024 * 8;
    const int S3 = S2 + PLANE;
    const int S4 = S3 + 16 * 72;
    const int S5 = S4 + 48 * NB * 8;
    for (int i = blockIdx.x * blockDim.x + threadIdx.x; i < S5;
         i += gridDim.x * blockDim.x) {
        if (i < S1) {
            int which = i >> 17, j = i & 131071;
            int G = j >> 7, col = j & 127;
            const float* W = which ? Whhd : Whhe;
            u16 ha, la, hb, lb;
            split16(W[G * HID + 2 * col], ha, la);
            split16(W[G * HID + 2 * col + 1], hb, lb);
            g_Wh[which][G][col] = (u32)ha | ((u32)hb << 16);
            g_Wl[which][G][col] = (u32)la | ((u32)lb << 16);
        } else if (i < S2) {
            int j = i - S1, G = j >> 3, cp = j & 7;
            u16 ha, la, hb, lb;
            split16(Wih[G * 16 + 2 * cp], ha, la);
            split16(Wih[G * 16 + 2 * cp + 1], hb, lb);
            g_Wxh[G][cp] = (u32)ha | ((u32)hb << 16);
            g_Wxl[G][cp] = (u32)la | ((u32)lb << 16);
        } else if (i < S3) {
            g_hpack[0][i - S2] = 0;
        } else if (i < S4) {
            g_ctr[i - S3] = 0;
        } else {
            int j = i - S4;
            int cp = j & 7, n = (j >> 3) & (NB - 1), t = j >> 16;
            u16 ha, la, hb, lb;
            split16(x[(n * 16 + 2 * cp) * 48 + t], ha, la);
            split16(x[(n * 16 + 2 * cp + 1) * 48 + t], hb, lb);
            g_xB[t][n][cp]     = (u32)ha | ((u32)hb << 16);
            g_xB[t][n][8 + cp] = (u32)la | ((u32)lb << 16);
        }
    }
}

// ---------------------------------------------------------------------------
__device__ __forceinline__ void loadA(int which, int m, int tid, char* sm)
{
    u32* AuHi = (u32*)(sm + OF_AU);
    u32* AuLo = (u32*)(sm + OF_AL);
    u32* Ax   = (u32*)(sm + OF_AX);
    for (int i = tid; i < 128 * 128; i += 512) {
        int r = i >> 7, j = i & 127;
        int G = ((r >> 5) << 8) + (m << 5) + (r & 31);
        int col = scol(j);
        AuHi[r * STR + col] = g_Wh[which][G][j];
        AuLo[r * STR + col] = g_Wl[which][G][j];
    }
    if (which == 0) {
        for (int i = tid; i < 128 * 8; i += 512) {
            int r = i >> 3, j = i & 7;
            int G = ((r >> 5) << 8) + (m << 5) + (r & 31);
            int col = ((j & 3) << 1) + ((j >> 2) & 1);
            Ax[r * 20 + col]     = g_Wxh[G][j];
            Ax[r * 20 + 8 + col] = g_Wxl[G][j];
        }
    }
}

// ---------------------------------------------------------------------------
__global__ void __launch_bounds__(512, 1)
lstm_mma(const float* __restrict__ enc_b, const float* __restrict__ dec_b,
         const float* __restrict__ dW, const float* __restrict__ db,
         float* __restrict__ out)
{
    extern __shared__ char sm[];
    float* sbias   = (float*)sm;                 // 128 floats
    u32*   AuHi    = (u32*)(sm + OF_AU);
    u32*   AuLo    = (u32*)(sm + OF_AL);
    u32*   Ax      = (u32*)(sm + OF_AX);
    u32*   Bx      = (u32*)(sm + OF_BX);
    u32*   BuHi    = (u32*)(sm + OF_BU);
    u32*   BuLo    = (u32*)(sm + OF_BL);
    float* bounce0 = (float*)(sm + OF_BU);       // alias (post-MMA), kh=0
    float* bounce1 = (float*)(sm + OF_BL);       // alias (post-MMA), kh=1

    const int tid = threadIdx.x, w = tid >> 5, lane = tid & 31;
    const int m = blockIdx.x & 7, s = blockIdx.x >> 3;
    const int gr = lane >> 2, tq = lane & 3;
    const int mg = w & 3, ns = (w >> 2) & 1, kh = w >> 3;  // m32 x n32 x K-half
    const int r0 = mg * 32, nb0 = ns * 32, ks0 = kh * 8;

    loadA(0, m, tid, sm);
    if (tid < 128)
        sbias[tid] = enc_b[((tid >> 5) << 8) + (m << 5) + (tid & 31)];
    __syncthreads();

    float cst[8][4];
    #pragma unroll
    for (int q = 0; q < 8; ++q)
        #pragma unroll
        for (int j = 0; j < 4; ++j) cst[q][j] = 0.f;

    int pp = 0;

    for (int t = 0; t < 72; ++t) {
        if (t == 48) {
            __syncthreads();
            loadA(1, m, tid, sm);
            if (tid < 128)
                sbias[tid] = dec_b[((tid >> 5) << 8) + (m << 5) + (tid & 31)];
            #pragma unroll
            for (int q = 0; q < 8; ++q)
                #pragma unroll
                for (int j = 0; j < 4; ++j) cst[q][j] = 0.f;
            __syncthreads();
        }

        #pragma unroll 1
        for (int q = 0; q < 8; ++q) {
            const int n0g = s * 512 + q * 64;
            // ---- build B tiles from packed h plane ----
            {
                const u32* hp = g_hpack[pp] + (size_t)n0g * 256;
                #pragma unroll
                for (int it = 0; it < 8; ++it) {
                    int i = it * 512 + tid;
                    int n = i >> 6, k4 = i & 63;
                    uint4 v = __ldg((const uint4*)(hp + n * 256) + k4);
                    u32 hi0 = prmt(v.x, v.y, 0x5410), hi1 = prmt(v.z, v.w, 0x5410);
                    u32 lo0 = prmt(v.x, v.y, 0x7632), lo1 = prmt(v.z, v.w, 0x7632);
                    int c0 = scol(2 * k4), c1 = scol(2 * k4 + 1);
                    BuHi[n * STR + c0] = hi0; BuHi[n * STR + c1] = hi1;
                    BuLo[n * STR + c0] = lo0; BuLo[n * STR + c1] = lo1;
                }
                if (t < 48) {
                    #pragma unroll
                    for (int it = 0; it < 2; ++it) {
                        int i = it * 512 + tid;
                        int n = i >> 4, j = i & 15;
                        int jj = j & 7, half = j >> 3;
                        int col = half * 8 + ((jj & 3) << 1) + (jj >> 2);
                        Bx[n * 20 + col] = g_xB[t][n0g + n][j];
                    }
                }
            }
            __syncthreads();

            // ---- MMAs: warp = m32 x n32, K-half ks0..ks0+7 ----
            float acc[2][4][4];
            #pragma unroll
            for (int mi = 0; mi < 2; ++mi)
                #pragma unroll
                for (int nt = 0; nt < 4; ++nt)
                    #pragma unroll
                    for (int j = 0; j < 4; ++j) acc[mi][nt][j] = 0.f;

            if (t < 48 && kh == 1) {        // x contribution on kh=1 warps
                uint2 AH[4], AL[4], BH[4], BL[4];
                #pragma unroll
                for (int rr = 0; rr < 4; ++rr) {
                    AH[rr] = *(const uint2*)&Ax[(r0 + 8 * rr + gr) * 20 + tq * 2];
                    AL[rr] = *(const uint2*)&Ax[(r0 + 8 * rr + gr) * 20 + 8 + tq * 2];
                }
                #pragma unroll
                for (int nt = 0; nt < 4; ++nt) {
                    BH[nt] = *(const uint2*)&Bx[(nb0 + nt * 8 + gr) * 20 + tq * 2];
                    BL[nt] = *(const uint2*)&Bx[(nb0 + nt * 8 + gr) * 20 + 8 + tq * 2];
                }
                #pragma unroll
                for (int mi = 0; mi < 2; ++mi)
                    #pragma unroll
                    for (int nt = 0; nt < 4; ++nt) {
                        mma16816(acc[mi][nt], AH[2*mi].x, AH[2*mi+1].x,
                                 AH[2*mi].y, AH[2*mi+1].y, BH[nt].x, BH[nt].y);
                        mma16816(acc[mi][nt], AH[2*mi].x, AH[2*mi+1].x,
                                 AH[2*mi].y, AH[2*mi+1].y, BL[nt].x, BL[nt].y);
                        mma16816(acc[mi][nt], AL[2*mi].x, AL[2*mi+1].x,
                                 AL[2*mi].y, AL[2*mi+1].y, BH[nt].x, BH[nt].y);
                    }
            }
            {
                const u32* ah = AuHi + (r0 + gr) * STR + tq * 2 + ks0 * 8;
                const u32* al = AuLo + (r0 + gr) * STR + tq * 2 + ks0 * 8;
                const u32* bh = BuHi + (nb0 + gr) * STR + tq * 2 + ks0 * 8;
                const u32* bl = BuLo + (nb0 + gr) * STR + tq * 2 + ks0 * 8;
                #pragma unroll 2
                for (int ks = 0; ks < 8; ++ks) {
                    uint2 AH[4], AL[4], BH[4], BL[4];
                    #pragma unroll
                    for (int rr = 0; rr < 4; ++rr) {
                        AH[rr] = *(const uint2*)(ah + rr * 8 * STR + ks * 8);
                        AL[rr] = *(const uint2*)(al + rr * 8 * STR + ks * 8);
                        BH[rr] = *(const uint2*)(bh + rr * 8 * STR + ks * 8);
                        BL[rr] = *(const uint2*)(bl + rr * 8 * STR + ks * 8);
                    }
                    #pragma unroll
                    for (int mi = 0; mi < 2; ++mi)
                        #pragma unroll
                        for (int nt = 0; nt < 4; ++nt) {
                            mma16816(acc[mi][nt], AH[2*mi].x, AH[2*mi+1].x,
                                     AH[2*mi].y, AH[2*mi+1].y, BH[nt].x, BH[nt].y);
                            mma16816(acc[mi][nt], AH[2*mi].x, AH[2*mi+1].x,
                                     AH[2*mi].y, AH[2*mi+1].y, BL[nt].x, BL[nt].y);
                            mma16816(acc[mi][nt], AL[2*mi].x, AL[2*mi+1].x,
                                     AL[2*mi].y, AL[2*mi+1].y, BH[nt].x, BH[nt].y);
                        }
                }
            }
            __syncthreads();        // B reads done -> bounce may overwrite

            // ---- bounce write (partial sums; bias added in cell update) ----
            {
                float* bnc = kh ? bounce1 : bounce0;
                #pragma unroll
                for (int mi = 0; mi < 2; ++mi) {
                    int rm = r0 + 16 * mi;
                    #pragma unroll
                    for (int nt = 0; nt < 4; ++nt) {
                        int n = nb0 + nt * 8 + 2 * tq;
                        bnc[(rm + gr) * 65 + n]         = acc[mi][nt][0];
                        bnc[(rm + gr) * 65 + n + 1]     = acc[mi][nt][1];
                        bnc[(rm + 8 + gr) * 65 + n]     = acc[mi][nt][2];
                        bnc[(rm + 8 + gr) * 65 + n + 1] = acc[mi][nt][3];
                    }
                }
            }
            __syncthreads();

            // ---- LSTM cell update + packed h store ----
            {
                int nn = tid >> 3, kq = tid & 7;
                u32 hv[4];
                #pragma unroll
                for (int j = 0; j < 4; ++j) {
                    int kk = kq * 4 + j;
                    float gi = bounce0[kk * 65 + nn]        + bounce1[kk * 65 + nn]        + sbias[kk];
                    float gf = bounce0[(32 + kk) * 65 + nn] + bounce1[(32 + kk) * 65 + nn] + sbias[32 + kk];
                    float gg = bounce0[(64 + kk) * 65 + nn] + bounce1[(64 + kk) * 65 + nn] + sbias[64 + kk];
                    float go = bounce0[(96 + kk) * 65 + nn] + bounce1[(96 + kk) * 65 + nn] + sbias[96 + kk];
                    float cn = sigf(gf) * cst[q][j] + sigf(gi) * tanh_(gg);
                    cst[q][j] = cn;
                    hv[j] = packsplit(sigf(go) * tanh_(cn));
                }
                u32* dst = g_hpack[pp ^ 1]
                           + (size_t)(n0g + nn) * 256 + m * 32 + kq * 4;
                *(uint4*)dst = make_uint4(hv[0], hv[1], hv[2], hv[3]);
            }
            __syncthreads();
        }

        // ---- slice barrier (8 peer CTAs) ----
        if (tid == 0) {
            __threadfence();
            atomicAdd(&g_ctr[s * 72 + t], 1);
            int v;
            do {
                asm volatile("ld.global.acquire.gpu.b32 %0, [%1];"
                             : "=r"(v) : "l"(&g_ctr[s * 72 + t]));
            } while (v < 8);
        }
        __syncthreads();
        pp ^= 1;

        // ---- decoder dense epilogue ----
        if (t >= 48) {
            int td = t - 48;
            const u32* hp2 = g_hpack[pp] + (size_t)(s * 512 + m * 64) * 256;
            u32*   hstage = (u32*)(sm + OF_BU);
            float* wstage = (float*)(sm + OF_AX);
            #pragma unroll
            for (int it = 0; it < 8; ++it) {
                int slot = it * 512 + tid;
                ((uint4*)hstage)[slot] = __ldg((const uint4*)hp2 + slot);
            }
            {
                float4 wv = __ldg((const float4*)(dW + td * 2048) + tid);
                int o = tid >> 6, k4 = tid & 63;
                *(float4*)&wstage[o * 260 + k4 * 4] = wv;
            }
            __syncthreads();
            int n_l = tid >> 3, o2 = tid & 7;
            const uint4*  hr = (const uint4*)(hstage + n_l * 256);
            const float4* wr = (const float4*)(wstage + o2 * 260);
            float a = __ldg(db + td * 8 + o2);
            #pragma unroll 8
            for (int k4 = 0; k4 < 64; ++k4) {
                uint4 hvv = hr[k4]; float4 wv = wr[k4];
                float2 p;
                p = bf2f(hvv.x); a = fmaf(p.x + p.y, wv.x, a);
                p = bf2f(hvv.y); a = fmaf(p.x + p.y, wv.y, a);
                p = bf2f(hvv.z); a = fmaf(p.x + p.y, wv.z, a);
                p = bf2f(hvv.w); a = fmaf(p.x + p.y, wv.w, a);
            }
            out[((size_t)(s * 512 + m * 64 + n_l) * 8 + o2) * 24 + td] = a;
            __syncthreads();
        }
    }
}

// ---------------------------------------------------------------------------
extern "C" void kernel_launch(void* const* d_in, const int* in_sizes, int n_in,
                              void* d_out, int out_size)
{
    (void)in_sizes; (void)n_in; (void)out_size;
    const float* x       = (const float*)d_in[0];
    const float* enc_Wih = (const float*)d_in[1];
    const float* enc_Whh = (const float*)d_in[2];
    const float* enc_b   = (const float*)d_in[3];
    const float* dec_Whh = (const float*)d_in[4];
    const float* dec_b   = (const float*)d_in[5];
    const float* dense_W = (const float*)d_in[6];
    const float* dense_b = (const float*)d_in[7];
    float* out = (float*)d_out;

    cudaFuncSetAttribute(lstm_mma,
                         cudaFuncAttributeMaxDynamicSharedMemorySize, SMEM_BYTES);

    prep_kernel<<<2048, 256>>>(x, enc_Wih, enc_Whh, dec_Whh);
    lstm_mma<<<128, 512, SMEM_BYTES>>>(enc_b, dec_b, dense_W, dense_b, out);
}

// round 14
// speedup vs baseline: 1.0993x; 1.0993x over previous
#include <cuda_runtime.h>
#include <cuda_bf16.h>

// Seq2seq LSTM via mma.sync.m16n8k16.bf16, split-bf16 (hi+lo, 3 products),
// fp32 accumulation. 128 persistent CTAs = 16 slices x 8 M-groups.
// R14 = R13 with the copyPlane size bug fixed (full 32KB tile copied).

typedef unsigned int u32;
typedef unsigned short u16;

#define HID 256
#define NB  8192
#define PLANE (NB * 128)           // u32 pairs per h plane
#define STR 136                    // u32 row stride (8 mod 32: conflict-free)

__device__ __align__(16) u32 g_Wh[2][1024][128];   // Whh hi pairs
__device__ __align__(16) u32 g_Wl[2][1024][128];   // Whh lo pairs
__device__ __align__(16) u32 g_Wxh[1024][8];       // Wih hi pairs
__device__ __align__(16) u32 g_Wxl[1024][8];       // Wih lo pairs
__device__ __align__(16) u32 g_xT[48 * 128 * 64 * 16]; // x tile images
__device__ __align__(16) u32 g_hHi[2][PLANE];      // h hi pairs, scol'd
__device__ __align__(16) u32 g_hLo[2][PLANE];      // h lo pairs, scol'd
__device__ __align__(16) float g_dWp[24 * 8 * 256];    // dense W, k-permuted
__device__ int g_ctr[16 * 72];

// ---- helpers ---------------------------------------------------------------
__device__ __forceinline__ u32 smem_u32(const void* p) {
    u32 a;
    asm("{ .reg .u64 t; cvta.to.shared.u64 t, %1; cvt.u32.u64 %0, t; }"
        : "=r"(a) : "l"(p));
    return a;
}
__device__ __forceinline__ void cpa16(u32 dst, const void* src) {
    asm volatile("cp.async.cg.shared.global [%0], [%1], 16;"
                 :: "r"(dst), "l"(src));
}
#define CPA_COMMIT() asm volatile("cp.async.commit_group;" ::: "memory")
#define CPA_WAIT0()  asm volatile("cp.async.wait_group 0;" ::: "memory")

__device__ __forceinline__ void mma16816(float* d, u32 a0, u32 a1, u32 a2,
                                         u32 a3, u32 b0, u32 b1) {
    asm volatile(
        "mma.sync.aligned.m16n8k16.row.col.f32.bf16.bf16.f32 "
        "{%0,%1,%2,%3}, {%4,%5,%6,%7}, {%8,%9}, {%0,%1,%2,%3};"
        : "+f"(d[0]), "+f"(d[1]), "+f"(d[2]), "+f"(d[3])
        : "r"(a0), "r"(a1), "r"(a2), "r"(a3), "r"(b0), "r"(b1));
}
__device__ __forceinline__ float sigf(float x) {
    return __fdividef(1.0f, 1.0f + __expf(-x));
}
__device__ __forceinline__ float tanh_(float x) {
    return 1.0f - __fdividef(2.0f, __expf(2.0f * x) + 1.0f);
}
__device__ __forceinline__ void split16(float v, u16& h, u16& l) {
    __nv_bfloat16 hb = __float2bfloat16(v);
    __nv_bfloat16 lb = __float2bfloat16(v - __bfloat162float(hb));
    h = *(u16*)&hb; l = *(u16*)&lb;
}
__device__ __forceinline__ float2 bf2f(u32 v) {
    return __bfloat1622float2(*(__nv_bfloat162*)&v);
}
// pair j -> storage col (scol): (b0,b1) of a fragment = one LDS.64
__device__ __forceinline__ int scol(int j) {
    return (j & ~7) + ((j & 3) << 1) + ((j >> 2) & 1);
}

// ---- SMEM byte layout -------------------------------------------------------
#define OF_BIAS 0
#define OF_AU   1024            // Whi tile 128xSTR u32 = 69632
#define OF_AL   70656           // Wlo tile 69632
#define OF_AX   140288          // Wx tile 128x20 u32 = 10240 (alias: dense W)
#define OF_BX0  150528          // x tile ping 64x20 u32 = 5120
#define OF_BX1  155648          // x tile pong 5120
#define OF_BU   160768          // h_hi tile 64xSTR = 34816 (alias: bounce)
#define OF_BL   195584          // h_lo tile 34816
#define SMEM_BYTES 230400

// ---------------------------------------------------------------------------
__global__ void prep_kernel(const float* __restrict__ x,
                            const float* __restrict__ Wih,
                            const float* __restrict__ Whhe,
                            const float* __restrict__ Whhd,
                            const float* __restrict__ dW)
{
    const int S1 = 2 * 1024 * 128;
    const int S2 = S1 + 1024 * 8;
    const int S3 = S2 + 2 * PLANE;
    const int S4 = S3 + 16 * 72;
    const int S5 = S4 + 48 * 128 * 64 * 8;
    const int S6 = S5 + 24 * 8 * 256;
    for (int i = blockIdx.x * blockDim.x + threadIdx.x; i < S6;
         i += gridDim.x * blockDim.x) {
        if (i < S1) {
            int which = i >> 17, j = i & 131071;
            int G = j >> 7, col = j & 127;
            const float* W = which ? Whhd : Whhe;
            u16 ha, la, hb, lb;
            split16(W[G * HID + 2 * col], ha, la);
            split16(W[G * HID + 2 * col + 1], hb, lb);
            g_Wh[which][G][col] = (u32)ha | ((u32)hb << 16);
            g_Wl[which][G][col] = (u32)la | ((u32)lb << 16);
        } else if (i < S2) {
            int j = i - S1, G = j >> 3, cp = j & 7;
            u16 ha, la, hb, lb;
            split16(Wih[G * 16 + 2 * cp], ha, la);
            split16(Wih[G * 16 + 2 * cp + 1], hb, lb);
            g_Wxh[G][cp] = (u32)ha | ((u32)hb << 16);
            g_Wxl[G][cp] = (u32)la | ((u32)lb << 16);
        } else if (i < S3) {
            int j = i - S2;
            if (j < PLANE) g_hHi[0][j] = 0; else g_hLo[0][j - PLANE] = 0;
        } else if (i < S4) {
            g_ctr[i - S3] = 0;
        } else if (i < S5) {
            int j = i - S4;
            int cp = j & 7, n = (j >> 3) & 63, sq = (j >> 9) & 127, t = j >> 16;
            u16 ha, la, hb, lb;
            int ng = sq * 64 + n;
            split16(x[(ng * 16 + 2 * cp) * 48 + t], ha, la);
            split16(x[(ng * 16 + 2 * cp + 1) * 48 + t], hb, lb);
            int sc = ((cp & 3) << 1) + (cp >> 2);      // scol within 8-group
            u32* dst = g_xT + ((t * 128 + sq) * 64 + n) * 16;
            dst[sc]     = (u32)ha | ((u32)hb << 16);
            dst[8 + sc] = (u32)la | ((u32)lb << 16);
        } else {
            int j = i - S5;
            int k = j & 255, o = (j >> 8) & 7, td = j >> 11;
            g_dWp[td * 2048 + o * 256 + 2 * scol(k >> 1) + (k & 1)] =
                dW[td * 2048 + o * 256 + k];
        }
    }
}

// ---------------------------------------------------------------------------
__device__ __forceinline__ void loadA(int which, int m, int tid, char* sm)
{
    u32* AuHi = (u32*)(sm + OF_AU);
    u32* AuLo = (u32*)(sm + OF_AL);
    u32* Ax   = (u32*)(sm + OF_AX);
    for (int i = tid; i < 128 * 128; i += 512) {
        int r = i >> 7, j = i & 127;
        int G = ((r >> 5) << 8) + (m << 5) + (r & 31);
        int col = scol(j);
        AuHi[r * STR + col] = g_Wh[which][G][j];
        AuLo[r * STR + col] = g_Wl[which][G][j];
    }
    if (which == 0) {
        for (int i = tid; i < 128 * 8; i += 512) {
            int r = i >> 3, j = i & 7;
            int G = ((r >> 5) << 8) + (m << 5) + (r & 31);
            int col = ((j & 3) << 1) + (j >> 2);
            Ax[r * 20 + col]     = g_Wxh[G][j];
            Ax[r * 20 + 8 + col] = g_Wxl[G][j];
        }
    }
}

// cp.async one 32KB h plane tile (64 rows x 128 u32 pairs) into padded tile.
// 512 threads x 4 chunks x 16B = 32KB (FIX: was 1 chunk = 8KB in R13).
__device__ __forceinline__ void copyPlane(u32 sb, int dstOff,
                                          const u32* __restrict__ src, int tid)
{
    int n = tid >> 3;
    #pragma unroll
    for (int it = 0; it < 4; ++it) {
        int c = (tid & 7) + it * 8;        // u32-pair col group (4 u32 each)
        cpa16(sb + dstOff + (n * STR + c * 4) * 4, src + n * 128 + c * 4);
    }
}
__device__ __forceinline__ void copyX(u32 sb, int dstOff,
                                      const u32* __restrict__ src, int tid)
{
    if (tid < 256) {
        int n = tid >> 2, c4 = tid & 3;
        cpa16(sb + dstOff + (n * 20 + c4 * 4) * 4, src + n * 16 + c4 * 4);
    }
}

// ---------------------------------------------------------------------------
__global__ void __launch_bounds__(512, 1)
lstm_mma(const float* __restrict__ enc_b, const float* __restrict__ dec_b,
         const float* __restrict__ db, float* __restrict__ out)
{
    extern __shared__ char sm[];
    const u32 sb = smem_u32(sm);
    float* sbias  = (float*)(sm + OF_BIAS);
    u32*   AuHi   = (u32*)(sm + OF_AU);
    u32*   AuLo   = (u32*)(sm + OF_AL);
    u32*   Ax     = (u32*)(sm + OF_AX);
    u32*   BuHi   = (u32*)(sm + OF_BU);
    u32*   BuLo   = (u32*)(sm + OF_BL);
    float* bounce = (float*)(sm + OF_BU);       // alias (post-MMA)

    const int tid = threadIdx.x, w = tid >> 5, lane = tid & 31;
    const int m = blockIdx.x & 7, s = blockIdx.x >> 3;
    const int gr = lane >> 2, tq = lane & 3;
    const int mg = w & 3, ns = w >> 2;          // warp = m32 x n16 tile
    const int r0 = mg * 32, nb0 = ns * 16;

    loadA(0, m, tid, sm);
    if (tid < 128)
        sbias[tid] = enc_b[((tid >> 5) << 8) + (m << 5) + (tid & 31)];
    // initial copies: B (s,0) both planes from plane 0; x tile (0, s*8)
    copyPlane(sb, OF_BU, g_hHi[0] + (size_t)(s * 8) * 64 * 128, tid);
    copyPlane(sb, OF_BL, g_hLo[0] + (size_t)(s * 8) * 64 * 128, tid);
    copyX(sb, OF_BX0, g_xT + (size_t)(0 * 128 + s * 8) * 1024, tid);
    CPA_COMMIT(); CPA_WAIT0();
    __syncthreads();

    float cst[8][4];
    #pragma unroll
    for (int q = 0; q < 8; ++q)
        #pragma unroll
        for (int j = 0; j < 4; ++j) cst[q][j] = 0.f;

    int pp = 0;

    for (int t = 0; t < 72; ++t) {
        #pragma unroll 1
        for (int q = 0; q < 8; ++q) {
            const int sq = s * 8 + q;
            const int bxOff = (q & 1) ? OF_BX1 : OF_BX0;

            // ---- MMAs: warp = m32 x n16, full K ----
            float acc[2][2][4];
            #pragma unroll
            for (int mi = 0; mi < 2; ++mi)
                #pragma unroll
                for (int nt = 0; nt < 2; ++nt)
                    #pragma unroll
                    for (int j = 0; j < 4; ++j) acc[mi][nt][j] = 0.f;

            if (t < 48) {
                u32* Bx = (u32*)(sm + bxOff);
                uint2 AH[4], AL[4], BH[2], BL[2];
                #pragma unroll
                for (int rr = 0; rr < 4; ++rr) {
                    AH[rr] = *(const uint2*)&Ax[(r0 + 8 * rr + gr) * 20 + tq * 2];
                    AL[rr] = *(const uint2*)&Ax[(r0 + 8 * rr + gr) * 20 + 8 + tq * 2];
                }
                #pragma unroll
                for (int nt = 0; nt < 2; ++nt) {
                    BH[nt] = *(const uint2*)&Bx[(nb0 + nt * 8 + gr) * 20 + tq * 2];
                    BL[nt] = *(const uint2*)&Bx[(nb0 + nt * 8 + gr) * 20 + 8 + tq * 2];
                }
                #pragma unroll
                for (int mi = 0; mi < 2; ++mi)
                    #pragma unroll
                    for (int nt = 0; nt < 2; ++nt) {
                        mma16816(acc[mi][nt], AH[2*mi].x, AH[2*mi+1].x,
                                 AH[2*mi].y, AH[2*mi+1].y, BH[nt].x, BH[nt].y);
                        mma16816(acc[mi][nt], AH[2*mi].x, AH[2*mi+1].x,
                                 AH[2*mi].y, AH[2*mi+1].y, BL[nt].x, BL[nt].y);
                        mma16816(acc[mi][nt], AL[2*mi].x, AL[2*mi+1].x,
                                 AL[2*mi].y, AL[2*mi+1].y, BH[nt].x, BH[nt].y);
                    }
            }
            {
                const u32* ah = AuHi + (r0 + gr) * STR + tq * 2;
                const u32* al = AuLo + (r0 + gr) * STR + tq * 2;
                const u32* bh = BuHi + (nb0 + gr) * STR + tq * 2;
                const u32* bl = BuLo + (nb0 + gr) * STR + tq * 2;
                #pragma unroll 2
                for (int ks = 0; ks < 16; ++ks) {
                    uint2 AH[4], AL[4], BH[2], BL[2];
                    #pragma unroll
                    for (int rr = 0; rr < 4; ++rr) {
                        AH[rr] = *(const uint2*)(ah + rr * 8 * STR + ks * 8);
                        AL[rr] = *(const uint2*)(al + rr * 8 * STR + ks * 8);
                    }
                    #pragma unroll
                    for (int nt = 0; nt < 2; ++nt) {
                        BH[nt] = *(const uint2*)(bh + nt * 8 * STR + ks * 8);
                        BL[nt] = *(const uint2*)(bl + nt * 8 * STR + ks * 8);
                    }
                    #pragma unroll
                    for (int mi = 0; mi < 2; ++mi)
                        #pragma unroll
                        for (int nt = 0; nt < 2; ++nt) {
                            mma16816(acc[mi][nt], AH[2*mi].x, AH[2*mi+1].x,
                                     AH[2*mi].y, AH[2*mi+1].y, BH[nt].x, BH[nt].y);
                            mma16816(acc[mi][nt], AH[2*mi].x, AH[2*mi+1].x,
                                     AH[2*mi].y, AH[2*mi+1].y, BL[nt].x, BL[nt].y);
                            mma16816(acc[mi][nt], AL[2*mi].x, AL[2*mi+1].x,
                                     AL[2*mi].y, AL[2*mi+1].y, BH[nt].x, BH[nt].y);
                        }
                }
            }
            __syncthreads();        // B reads done

            // prefetch next chunk's B-lo (+x) under bounce/update (BuLo free)
            if (q < 7) {
                copyPlane(sb, OF_BL,
                          g_hLo[pp] + (size_t)(sq + 1) * 64 * 128, tid);
                if (t < 48)
                    copyX(sb, (q & 1) ? OF_BX0 : OF_BX1,
                          g_xT + (size_t)(t * 128 + sq + 1) * 1024, tid);
                CPA_COMMIT();
            }

            // ---- bounce write (+bias) into BuHi region ----
            #pragma unroll
            for (int mi = 0; mi < 2; ++mi) {
                int rm = r0 + 16 * mi;
                float b0 = sbias[rm + gr], b1 = sbias[rm + 8 + gr];
                #pragma unroll
                for (int nt = 0; nt < 2; ++nt) {
                    int n = nb0 + nt * 8 + 2 * tq;
                    bounce[(rm + gr) * 65 + n]         = acc[mi][nt][0] + b0;
                    bounce[(rm + gr) * 65 + n + 1]     = acc[mi][nt][1] + b0;
                    bounce[(rm + 8 + gr) * 65 + n]     = acc[mi][nt][2] + b1;
                    bounce[(rm + 8 + gr) * 65 + n + 1] = acc[mi][nt][3] + b1;
                }
            }
            __syncthreads();

            // ---- LSTM cell update + split/scol'd h store ----
            {
                int nn = tid >> 3, kq = tid & 7;
                float hval[4];
                #pragma unroll
                for (int j = 0; j < 4; ++j) {
                    int kk = kq * 4 + j;
                    float gi = bounce[kk * 65 + nn];
                    float gf = bounce[(32 + kk) * 65 + nn];
                    float gg = bounce[(64 + kk) * 65 + nn];
                    float go = bounce[(96 + kk) * 65 + nn];
                    float cn = sigf(gf) * cst[q][j] + sigf(gi) * tanh_(gg);
                    cst[q][j] = cn;
                    hval[j] = sigf(go) * tanh_(cn);
                }
                u16 h0, l0, h1, l1, h2, l2, h3, l3;
                split16(hval[0], h0, l0); split16(hval[1], h1, l1);
                split16(hval[2], h2, l2); split16(hval[3], h3, l3);
                size_t row = (size_t)(sq * 64 + nn) * 128;
                int c0 = m * 16 + scol(2 * kq);
                int c1 = m * 16 + scol(2 * kq + 1);
                g_hHi[pp ^ 1][row + c0] = (u32)h0 | ((u32)h1 << 16);
                g_hHi[pp ^ 1][row + c1] = (u32)h2 | ((u32)h3 << 16);
                g_hLo[pp ^ 1][row + c0] = (u32)l0 | ((u32)l1 << 16);
                g_hLo[pp ^ 1][row + c1] = (u32)l2 | ((u32)l3 << 16);
            }
            __syncthreads();        // bounce reads done -> BuHi free

            if (q < 7) {
                copyPlane(sb, OF_BU,
                          g_hHi[pp] + (size_t)(sq + 1) * 64 * 128, tid);
                CPA_COMMIT();
            }
            CPA_WAIT0();
            __syncthreads();
        }

        // ---- slice barrier (8 peer CTAs) ----
        if (tid == 0) {
            __threadfence();
            atomicAdd(&g_ctr[s * 72 + t], 1);
            int v;
            do {
                asm volatile("ld.global.acquire.gpu.b32 %0, [%1];"
                             : "=r"(v) : "l"(&g_ctr[s * 72 + t]));
            } while (v < 8);
        }
        __syncthreads();
        pp ^= 1;

        // ---- decoder dense epilogue ----
        if (t >= 48) {
            int td = t - 48;
            const size_t hb = (size_t)(s * 8 + m) * 64 * 128;
            copyPlane(sb, OF_BU, g_hHi[pp] + hb, tid);
            copyPlane(sb, OF_BL, g_hLo[pp] + hb, tid);
            float* wstage = (float*)(sm + OF_AX);
            {
                float4 wv = *(const float4*)(g_dWp + td * 2048 + tid * 4);
                int o = tid >> 6, k4 = tid & 63;
                *(float4*)&wstage[o * 260 + k4 * 4] = wv;
            }
            CPA_COMMIT(); CPA_WAIT0();
            __syncthreads();
            int n_l = tid >> 3, o2 = tid & 7;
            const u32* hh = BuHi + n_l * STR;
            const u32* hl = BuLo + n_l * STR;
            const float2* wr = (const float2*)&wstage[o2 * 260];
            float a = __ldg(db + td * 8 + o2);
            #pragma unroll 8
            for (int pi = 0; pi < 128; ++pi) {
                float2 ph = bf2f(hh[pi]), pl = bf2f(hl[pi]);
                float2 wv = wr[pi];
                a = fmaf(ph.x + pl.x, wv.x, a);
                a = fmaf(ph.y + pl.y, wv.y, a);
            }
            out[((size_t)(s * 512 + m * 64 + n_l) * 8 + o2) * 24 + td] = a;
            __syncthreads();
        }

        if (t == 47) {
            loadA(1, m, tid, sm);
            if (tid < 128)
                sbias[tid] = dec_b[((tid >> 5) << 8) + (m << 5) + (tid & 31)];
            #pragma unroll
            for (int q = 0; q < 8; ++q)
                #pragma unroll
                for (int j = 0; j < 4; ++j) cst[q][j] = 0.f;
        }

        if (t < 71) {       // copies for (t+1, q=0)
            copyPlane(sb, OF_BU, g_hHi[pp] + (size_t)(s * 8) * 64 * 128, tid);
            copyPlane(sb, OF_BL, g_hLo[pp] + (size_t)(s * 8) * 64 * 128, tid);
            if (t < 47)
                copyX(sb, OF_BX0,
                      g_xT + (size_t)((t + 1) * 128 + s * 8) * 1024, tid);
            CPA_COMMIT(); CPA_WAIT0();
        }
        __syncthreads();
    }
}

// ---------------------------------------------------------------------------
extern "C" void kernel_launch(void* const* d_in, const int* in_sizes, int n_in,
                              void* d_out, int out_size)
{
    (void)in_sizes; (void)n_in; (void)out_size;
    const float* x       = (const float*)d_in[0];
    const float* enc_Wih = (const float*)d_in[1];
    const float* enc_Whh = (const float*)d_in[2];
    const float* enc_b   = (const float*)d_in[3];
    const float* dec_Whh = (const float*)d_in[4];
    const float* dec_b   = (const float*)d_in[5];
    const float* dense_W = (const float*)d_in[6];
    const float* dense_b = (const float*)d_in[7];
    float* out = (float*)d_out;

    cudaFuncSetAttribute(lstm_mma,
                         cudaFuncAttributeMaxDynamicSharedMemorySize, SMEM_BYTES);

    prep_kernel<<<2048, 256>>>(x, enc_Wih, enc_Whh, dec_Whh, dense_W);
    lstm_mma<<<128, 512, SMEM_BYTES>>>(enc_b, dec_b, dense_b, out);
}